// round 6
// baseline (speedup 1.0000x reference)
#include <cuda_runtime.h>
#include <math_constants.h>

// Until: out[b,t,x] = min(phi[b,t,x], max(psi[b,t,x], out[b,t-1,x])), out[-1] = -1e6.
// Single-pass chained scan (decoupled lookback). Monoid f(v)=min(A,max(B,v)):
//   compose (later∘earlier): A' = min(A2, max(B2, A1)), B' = max(B1, B2).
// R6: 64-thread blocks, 24 CTAs/SM — decorrelate serial sections across many
// resident blocks so the memory pipe never drains.

#define B_   64
#define T_   8192
#define X_   32
#define TC_  128                // time steps per chunk
#define C_   (T_ / TC_)         // 64 chunks per batch
#define NB_  (B_ * C_)          // 4096 blocks
#define SL_  8                  // t-slices per block (one slice per thread-octet)
#define PT_  (TC_ / SL_)        // 16 steps per thread
#define LARGE_ 1.0e6f

__device__ float g_A[NB_ * X_];   // chunk aggregate A
__device__ float g_Bv[NB_ * X_];  // chunk aggregate B
__device__ float g_P[NB_ * X_];   // chunk inclusive prefix value
__device__ int   g_flag[NB_];     // epoch-tagged: 2e+1 aggregate, 2e+2 prefix
__device__ int   g_ticket;        // never reset; epoch = ticket / NB_

__global__ void __launch_bounds__(64, 24) until_scan(const float* __restrict__ phi,
                                                     const float* __restrict__ psi,
                                                     float* __restrict__ out) {
    __shared__ float sA[SL_][X_];
    __shared__ float sB[SL_][X_];
    __shared__ float sC[SL_][X_];   // carry entering each slice
    __shared__ int s_tic;

    const int tid = threadIdx.x;
    if (tid == 0) s_tic = atomicAdd(&g_ticket, 1);
    __syncthreads();
    const int traw = s_tic;
    const int e    = traw / NB_;          // epoch (graph replay count)
    const int v    = traw - e * NB_;
    const int b    = v % B_;              // breadth-first over chunks
    const int c    = v / B_;
    const int bc   = b * C_ + c;
    const int FLAG_AGG = 2 * e + 1;
    const int FLAG_PRE = 2 * e + 2;

    const int xq = (tid & 7) * 4;         // 4 consecutive x per thread
    const int s  = tid >> 3;              // slice 0..7

    const size_t base = (size_t)b * T_ * X_ + (size_t)(c * TC_ + s * PT_) * X_ + xq;
    const float4* pp = (const float4*)(phi + base);
    const float4* qq = (const float4*)(psi + base);

    // ---------- phase 1: streaming slice aggregate ----------
    float4 A  = make_float4( CUDART_INF_F,  CUDART_INF_F,  CUDART_INF_F,  CUDART_INF_F);
    float4 Bc = make_float4(-CUDART_INF_F, -CUDART_INF_F, -CUDART_INF_F, -CUDART_INF_F);
#pragma unroll
    for (int i = 0; i < PT_; i++) {
        float4 p = pp[i * (X_ / 4)];
        float4 q = qq[i * (X_ / 4)];
        A.x = fminf(p.x, fmaxf(q.x, A.x));  Bc.x = fmaxf(q.x, Bc.x);
        A.y = fminf(p.y, fmaxf(q.y, A.y));  Bc.y = fmaxf(q.y, Bc.y);
        A.z = fminf(p.z, fmaxf(q.z, A.z));  Bc.z = fmaxf(q.z, Bc.z);
        A.w = fminf(p.w, fmaxf(q.w, A.w));  Bc.w = fmaxf(q.w, Bc.w);
    }
    sA[s][xq + 0] = A.x;  sA[s][xq + 1] = A.y;  sA[s][xq + 2] = A.z;  sA[s][xq + 3] = A.w;
    sB[s][xq + 0] = Bc.x; sB[s][xq + 1] = Bc.y; sB[s][xq + 2] = Bc.z; sB[s][xq + 3] = Bc.w;
    __syncthreads();

    // ---------- fold + lookback + slice carries (warp 0, lane = x) ----------
    if (tid < 32) {
        const int x = tid;
        float Ab =  CUDART_INF_F;
        float Bb = -CUDART_INF_F;
#pragma unroll
        for (int j = 0; j < SL_; j++) {
            Ab = fminf(sA[j][x], fmaxf(sB[j][x], Ab));
            Bb = fmaxf(sB[j][x], Bb);
        }

        // Publish aggregate ONLY for c>0: chunk 0 goes straight to prefix,
        // so lookback never crosses a batch boundary.
        if (c > 0) {
            g_A[bc * X_ + x]  = Ab;
            g_Bv[bc * X_ + x] = Bb;
            __threadfence();
            __syncwarp();
            if (x == 0) *(volatile int*)&g_flag[bc] = FLAG_AGG;
        }

        float vin;
        if (c == 0) {
            vin = -LARGE_;
        } else {
            float accA =  CUDART_INF_F;
            float accB = -CUDART_INF_F;
            int j = bc - 1;
            while (true) {
                int f;
                do { f = *(volatile int*)&g_flag[j]; } while (f < FLAG_AGG);
                __threadfence();
                if (f == FLAG_PRE) {
                    vin = fminf(accA, fmaxf(accB, g_P[j * X_ + x]));
                    break;
                }
                float Aj = g_A[j * X_ + x];
                float Bj = g_Bv[j * X_ + x];
                accA = fminf(accA, fmaxf(accB, Aj));
                accB = fmaxf(accB, Bj);
                j--;
            }
        }

        // carries entering each slice + publish inclusive prefix
        float g = vin;
#pragma unroll
        for (int j = 0; j < SL_; j++) {
            sC[j][x] = g;
            g = fminf(sA[j][x], fmaxf(sB[j][x], g));
        }
        g_P[bc * X_ + x] = g;
        __threadfence();
        __syncwarp();
        if (x == 0) *(volatile int*)&g_flag[bc] = FLAG_PRE;
    }
    __syncthreads();

    // ---------- phase 2: reload (mostly L2), apply carry, stream out ----------
    float4 vc = make_float4(sC[s][xq + 0], sC[s][xq + 1], sC[s][xq + 2], sC[s][xq + 3]);
    float4* oo = (float4*)(out + base);
#pragma unroll
    for (int i = 0; i < PT_; i++) {
        float4 p = __ldcs(&pp[i * (X_ / 4)]);
        float4 q = __ldcs(&qq[i * (X_ / 4)]);
        vc.x = fminf(p.x, fmaxf(q.x, vc.x));
        vc.y = fminf(p.y, fmaxf(q.y, vc.y));
        vc.z = fminf(p.z, fmaxf(q.z, vc.z));
        vc.w = fminf(p.w, fmaxf(q.w, vc.w));
        __stcs(&oo[i * (X_ / 4)], vc);
    }
}

extern "C" void kernel_launch(void* const* d_in, const int* in_sizes, int n_in,
                              void* d_out, int out_size) {
    const float* phi = (const float*)d_in[0];
    const float* psi = (const float*)d_in[1];
    float* out = (float*)d_out;

    until_scan<<<NB_, 64>>>(phi, psi, out);
}

// round 7
// speedup vs baseline: 1.0246x; 1.0246x over previous
#include <cuda_runtime.h>
#include <math_constants.h>

// Until: out[b,t,x] = min(phi[b,t,x], max(psi[b,t,x], out[b,t-1,x])), out[-1] = -1e6.
// Single-pass chained scan (decoupled lookback). Monoid f(v)=min(A,max(B,v)):
//   compose (later∘earlier): A' = min(A2, max(B2, A1)), B' = max(B1, B2).
// R7: tile cached in static smem (44KB) -> inputs read from DRAM exactly once,
// phase 2 is smem + streaming stores. 5 CTAs/SM, 5.5 waves pipeline the chain.

#define B_   64
#define T_   8192
#define X_   32
#define TC_  128                // time steps per chunk
#define C_   (T_ / TC_)         // 64 chunks per batch
#define NB_  (B_ * C_)          // 4096 blocks
#define SL_  32                 // t-slices per block
#define PT_  (TC_ / SL_)        // 4 steps per thread
#define LARGE_ 1.0e6f

__device__ float g_A[NB_ * X_];   // chunk aggregate A
__device__ float g_Bv[NB_ * X_];  // chunk aggregate B
__device__ float g_P[NB_ * X_];   // chunk inclusive prefix value
__device__ int   g_flag[NB_];     // epoch-tagged: 2e+1 aggregate, 2e+2 prefix
__device__ int   g_ticket;        // never reset; epoch = ticket / NB_

__global__ void __launch_bounds__(256, 5) until_scan(const float* __restrict__ phi,
                                                     const float* __restrict__ psi,
                                                     float* __restrict__ out) {
    __shared__ float4 sP[TC_][X_ / 4];   // 16KB  cached phi tile
    __shared__ float4 sQ[TC_][X_ / 4];   // 16KB  cached psi tile
    __shared__ float  sA[SL_][X_];       // 4KB   per-slice aggregate A
    __shared__ float  sB[SL_][X_];       // 4KB   per-slice aggregate B
    __shared__ float  sC[SL_][X_];       // 4KB   carry entering each slice
    __shared__ int s_tic;

    const int tid = threadIdx.x;
    if (tid == 0) s_tic = atomicAdd(&g_ticket, 1);
    __syncthreads();
    const int traw = s_tic;
    const int e    = traw / NB_;          // epoch (graph replay count)
    const int v    = traw - e * NB_;
    const int b    = v % B_;              // breadth-first over chunks
    const int c    = v / B_;
    const int bc   = b * C_ + c;
    const int FLAG_AGG = 2 * e + 1;
    const int FLAG_PRE = 2 * e + 2;

    const int xg = tid & 7;               // float4 group along x
    const int xq = xg * 4;
    const int s  = tid >> 3;              // slice 0..31

    const size_t base = (size_t)b * T_ * X_ + (size_t)(c * TC_ + s * PT_) * X_ + xq;
    const float4* pp = (const float4*)(phi + base);
    const float4* qq = (const float4*)(psi + base);

    // ---------- phase 1: single DRAM read, park tile in smem, aggregate ----------
    float4 A  = make_float4( CUDART_INF_F,  CUDART_INF_F,  CUDART_INF_F,  CUDART_INF_F);
    float4 Bc = make_float4(-CUDART_INF_F, -CUDART_INF_F, -CUDART_INF_F, -CUDART_INF_F);
#pragma unroll
    for (int i = 0; i < PT_; i++) {
        float4 p = __ldcs(&pp[i * (X_ / 4)]);
        float4 q = __ldcs(&qq[i * (X_ / 4)]);
        sP[s * PT_ + i][xg] = p;
        sQ[s * PT_ + i][xg] = q;
        A.x = fminf(p.x, fmaxf(q.x, A.x));  Bc.x = fmaxf(q.x, Bc.x);
        A.y = fminf(p.y, fmaxf(q.y, A.y));  Bc.y = fmaxf(q.y, Bc.y);
        A.z = fminf(p.z, fmaxf(q.z, A.z));  Bc.z = fmaxf(q.z, Bc.z);
        A.w = fminf(p.w, fmaxf(q.w, A.w));  Bc.w = fmaxf(q.w, Bc.w);
    }
    sA[s][xq + 0] = A.x;  sA[s][xq + 1] = A.y;  sA[s][xq + 2] = A.z;  sA[s][xq + 3] = A.w;
    sB[s][xq + 0] = Bc.x; sB[s][xq + 1] = Bc.y; sB[s][xq + 2] = Bc.z; sB[s][xq + 3] = Bc.w;
    __syncthreads();

    // ---------- fold + lookback + slice carries (warp 0, lane = x) ----------
    if (tid < 32) {
        const int x = tid;
        float Ab =  CUDART_INF_F;
        float Bb = -CUDART_INF_F;
#pragma unroll
        for (int j = 0; j < SL_; j++) {
            Ab = fminf(sA[j][x], fmaxf(sB[j][x], Ab));
            Bb = fmaxf(sB[j][x], Bb);
        }

        // Publish aggregate ONLY for c>0: chunk 0 goes straight to prefix,
        // so lookback never crosses a batch boundary.
        if (c > 0) {
            g_A[bc * X_ + x]  = Ab;
            g_Bv[bc * X_ + x] = Bb;
            __threadfence();
            __syncwarp();
            if (x == 0) *(volatile int*)&g_flag[bc] = FLAG_AGG;
        }

        float vin;
        if (c == 0) {
            vin = -LARGE_;
        } else {
            float accA =  CUDART_INF_F;
            float accB = -CUDART_INF_F;
            int j = bc - 1;
            while (true) {
                int f;
                do { f = *(volatile int*)&g_flag[j]; } while (f < FLAG_AGG);
                __threadfence();
                if (f == FLAG_PRE) {
                    vin = fminf(accA, fmaxf(accB, g_P[j * X_ + x]));
                    break;
                }
                float Aj = g_A[j * X_ + x];
                float Bj = g_Bv[j * X_ + x];
                accA = fminf(accA, fmaxf(accB, Aj));
                accB = fmaxf(accB, Bj);
                j--;
            }
        }

        // carries entering each slice + publish inclusive prefix
        float g = vin;
#pragma unroll
        for (int j = 0; j < SL_; j++) {
            sC[j][x] = g;
            g = fminf(sA[j][x], fmaxf(sB[j][x], g));
        }
        g_P[bc * X_ + x] = g;
        __threadfence();
        __syncwarp();
        if (x == 0) *(volatile int*)&g_flag[bc] = FLAG_PRE;
    }
    __syncthreads();

    // ---------- phase 2: smem replay, apply carry, stream out ----------
    float4 vc = make_float4(sC[s][xq + 0], sC[s][xq + 1], sC[s][xq + 2], sC[s][xq + 3]);
    float4* oo = (float4*)(out + base);
#pragma unroll
    for (int i = 0; i < PT_; i++) {
        float4 p = sP[s * PT_ + i][xg];
        float4 q = sQ[s * PT_ + i][xg];
        vc.x = fminf(p.x, fmaxf(q.x, vc.x));
        vc.y = fminf(p.y, fmaxf(q.y, vc.y));
        vc.z = fminf(p.z, fmaxf(q.z, vc.z));
        vc.w = fminf(p.w, fmaxf(q.w, vc.w));
        __stcs(&oo[i * (X_ / 4)], vc);
    }
}

extern "C" void kernel_launch(void* const* d_in, const int* in_sizes, int n_in,
                              void* d_out, int out_size) {
    const float* phi = (const float*)d_in[0];
    const float* psi = (const float*)d_in[1];
    float* out = (float*)d_out;

    until_scan<<<NB_, 256>>>(phi, psi, out);
}

// round 8
// speedup vs baseline: 1.2821x; 1.2513x over previous
#include <cuda_runtime.h>
#include <math_constants.h>

// Until: out[b,t,x] = min(phi[b,t,x], max(psi[b,t,x], out[b,t-1,x])), out[-1] = -1e6.
// Single-pass chained scan (decoupled lookback). Monoid f(v)=min(A,max(B,v)):
//   compose (later∘earlier): A' = min(A2, max(B2, A1)), B' = max(B1, B2).
// R8: warp-specialized lookback — warp 8 resolves the incoming carry WHILE
// warps 0-7 stream phase 1, so the chain latency hides under the DRAM time.

#define B_   64
#define T_   8192
#define X_   32
#define TC_  256                // time steps per chunk
#define C_   (T_ / TC_)         // 32 chunks per batch
#define NB_  (B_ * C_)          // 2048 blocks
#define SL_  32                 // t-slices per block
#define PT_  (TC_ / SL_)        // 8 steps per thread
#define NW_  8                  // loader warps
#define SPW_ (SL_ / NW_)        // 4 slices per loader warp
#define NT_  288                // 8 loader warps + 1 lookback warp
#define LARGE_ 1.0e6f

__device__ float g_A[NB_ * X_];   // chunk aggregate A
__device__ float g_Bv[NB_ * X_];  // chunk aggregate B
__device__ float g_P[NB_ * X_];   // chunk inclusive prefix value
__device__ int   g_flag[NB_];     // epoch-tagged: 2e+1 aggregate, 2e+2 prefix
__device__ int   g_ticket;        // never reset; epoch = ticket / NB_

__global__ void __launch_bounds__(NT_, 4) until_scan(const float* __restrict__ phi,
                                                     const float* __restrict__ psi,
                                                     float* __restrict__ out) {
    __shared__ float sA[SL_][X_];     // per-slice aggregate A
    __shared__ float sB[SL_][X_];     // per-slice aggregate B
    __shared__ float sWA[NW_][X_];    // per-warp fold
    __shared__ float sWB[NW_][X_];
    __shared__ float sGC[NW_][X_];    // carry entering each warp's slice group
    __shared__ float sFA[X_];         // block aggregate
    __shared__ float sFB[X_];
    __shared__ float sVin[X_];        // resolved incoming carry
    __shared__ int s_tic;

    const int tid = threadIdx.x;
    if (tid == 0) s_tic = atomicAdd(&g_ticket, 1);
    __syncthreads();
    const int traw = s_tic;
    const int e    = traw / NB_;          // epoch (graph replay count)
    const int v    = traw - e * NB_;
    const int b    = v % B_;              // breadth-first over chunks
    const int c    = v / B_;
    const int bc   = b * C_ + c;
    const int FLAG_AGG = 2 * e + 1;
    const int FLAG_PRE = 2 * e + 2;

    if (tid < 256) {
        // ================= loader warps 0-7 =================
        const int xg = tid & 7;
        const int xq = xg * 4;
        const int s  = tid >> 3;          // slice 0..31
        const int w  = tid >> 5;          // warp 0..7
        const int lane = tid & 31;

        const size_t base = (size_t)b * T_ * X_ + (size_t)(c * TC_ + s * PT_) * X_ + xq;
        const float4* pp = (const float4*)(phi + base);
        const float4* qq = (const float4*)(psi + base);

        // ---- phase 1: streaming slice aggregate (keeps lines in L2) ----
        float4 A  = make_float4( CUDART_INF_F,  CUDART_INF_F,  CUDART_INF_F,  CUDART_INF_F);
        float4 Bc = make_float4(-CUDART_INF_F, -CUDART_INF_F, -CUDART_INF_F, -CUDART_INF_F);
#pragma unroll
        for (int i = 0; i < PT_; i++) {
            float4 p = pp[i * (X_ / 4)];
            float4 q = qq[i * (X_ / 4)];
            A.x = fminf(p.x, fmaxf(q.x, A.x));  Bc.x = fmaxf(q.x, Bc.x);
            A.y = fminf(p.y, fmaxf(q.y, A.y));  Bc.y = fmaxf(q.y, Bc.y);
            A.z = fminf(p.z, fmaxf(q.z, A.z));  Bc.z = fmaxf(q.z, Bc.z);
            A.w = fminf(p.w, fmaxf(q.w, A.w));  Bc.w = fmaxf(q.w, Bc.w);
        }
        sA[s][xq + 0] = A.x;  sA[s][xq + 1] = A.y;  sA[s][xq + 2] = A.z;  sA[s][xq + 3] = A.w;
        sB[s][xq + 0] = Bc.x; sB[s][xq + 1] = Bc.y; sB[s][xq + 2] = Bc.z; sB[s][xq + 3] = Bc.w;
        __syncwarp();

        // ---- per-warp fold of its 4 slices (lane = x) ----
        {
            float wA =  CUDART_INF_F;
            float wB = -CUDART_INF_F;
#pragma unroll
            for (int j = 0; j < SPW_; j++) {
                const int sl = w * SPW_ + j;
                wA = fminf(sA[sl][lane], fmaxf(sB[sl][lane], wA));
                wB = fmaxf(sB[sl][lane], wB);
            }
            sWA[w][lane] = wA;
            sWB[w][lane] = wB;
        }
        asm volatile("bar.sync 1, 256;" ::: "memory");   // loaders only

        // ---- warp 0: block fold + EARLY aggregate publish (no carry needed) ----
        if (tid < 32) {
            const int x = tid;
            float Ab =  CUDART_INF_F;
            float Bb = -CUDART_INF_F;
#pragma unroll
            for (int j = 0; j < NW_; j++) {
                Ab = fminf(sWA[j][x], fmaxf(sWB[j][x], Ab));
                Bb = fmaxf(sWB[j][x], Bb);
            }
            sFA[x] = Ab;
            sFB[x] = Bb;
            // chunk 0 never publishes AGG -> lookback can't cross batch boundary
            if (c > 0) {
                g_A[bc * X_ + x]  = Ab;
                g_Bv[bc * X_ + x] = Bb;
                __threadfence();
                __syncwarp();
                if (x == 0) *(volatile int*)&g_flag[bc] = FLAG_AGG;
            }
        }

        __syncthreads();   // rendezvous with lookback warp (vin + sFA/sFB ready)
        __syncthreads();   // warp 8 publishes prefix + fills sGC between these

        // ---- per-thread slice carry, then phase 2: L2 reload + store ----
        float v0 = sGC[w][xq + 0];
        float v1 = sGC[w][xq + 1];
        float v2 = sGC[w][xq + 2];
        float v3 = sGC[w][xq + 3];
        for (int j = w * SPW_; j < s; j++) {
            v0 = fminf(sA[j][xq + 0], fmaxf(sB[j][xq + 0], v0));
            v1 = fminf(sA[j][xq + 1], fmaxf(sB[j][xq + 1], v1));
            v2 = fminf(sA[j][xq + 2], fmaxf(sB[j][xq + 2], v2));
            v3 = fminf(sA[j][xq + 3], fmaxf(sB[j][xq + 3], v3));
        }
        float4 vc = make_float4(v0, v1, v2, v3);

        float4* oo = (float4*)(out + base);
#pragma unroll
        for (int i = 0; i < PT_; i++) {
            float4 p = __ldcs(&pp[i * (X_ / 4)]);
            float4 q = __ldcs(&qq[i * (X_ / 4)]);
            vc.x = fminf(p.x, fmaxf(q.x, vc.x));
            vc.y = fminf(p.y, fmaxf(q.y, vc.y));
            vc.z = fminf(p.z, fmaxf(q.z, vc.z));
            vc.w = fminf(p.w, fmaxf(q.w, vc.w));
            __stcs(&oo[i * (X_ / 4)], vc);
        }
    } else {
        // ================= warp 8: lookback specialist =================
        const int x = tid & 31;

        // resolve incoming carry CONCURRENTLY with phase 1
        float vin;
        if (c == 0) {
            vin = -LARGE_;
        } else {
            float accA =  CUDART_INF_F;
            float accB = -CUDART_INF_F;
            int j = bc - 1;
            while (true) {
                int f;
                do { f = *(volatile int*)&g_flag[j]; } while (f < FLAG_AGG);
                __threadfence();
                if (f == FLAG_PRE) {
                    vin = fminf(accA, fmaxf(accB, g_P[j * X_ + x]));
                    break;
                }
                float Aj = g_A[j * X_ + x];
                float Bj = g_Bv[j * X_ + x];
                accA = fminf(accA, fmaxf(accB, Aj));
                accB = fmaxf(accB, Bj);
                j--;
            }
        }
        sVin[x] = vin;

        __syncthreads();   // loaders finished phase 1; sFA/sFB valid

        // publish inclusive prefix ASAP (shortest tier-to-tier latency)
        float pre = fminf(sFA[x], fmaxf(sFB[x], vin));
        g_P[bc * X_ + x] = pre;
        __threadfence();
        __syncwarp();
        if (x == 0) *(volatile int*)&g_flag[bc] = FLAG_PRE;

        // carries entering each loader warp's slice group
        float g = vin;
#pragma unroll
        for (int j = 0; j < NW_; j++) {
            sGC[j][x] = g;
            g = fminf(sWA[j][x], fmaxf(sWB[j][x], g));
        }

        __syncthreads();   // release loaders into phase 2
    }
}

extern "C" void kernel_launch(void* const* d_in, const int* in_sizes, int n_in,
                              void* d_out, int out_size) {
    const float* phi = (const float*)d_in[0];
    const float* psi = (const float*)d_in[1];
    float* out = (float*)d_out;

    until_scan<<<NB_, NT_>>>(phi, psi, out);
}

// round 9
// speedup vs baseline: 1.3371x; 1.0429x over previous
#include <cuda_runtime.h>
#include <math_constants.h>

// Until: out[b,t,x] = min(phi[b,t,x], max(psi[b,t,x], out[b,t-1,x])), out[-1] = -1e6.
// Single-pass chained scan (decoupled lookback). Monoid f(v)=min(A,max(B,v)):
//   compose (later∘earlier): A' = min(A2, max(B2, A1)), B' = max(B1, B2).
// R9: R4 base (best scan: 49.4us) + hierarchical fold/carry (short warp0 serial
// path) + occupancy 6 CTAs/SM via launch_bounds + epoch flags (no reset).

#define B_   64
#define T_   8192
#define X_   32
#define TC_  256                // time steps per chunk
#define C_   (T_ / TC_)         // 32 chunks per batch
#define NB_  (B_ * C_)          // 2048 blocks
#define SL_  32                 // t-slices per block
#define PT_  (TC_ / SL_)        // 8 steps per thread
#define NW_  8                  // warps per block
#define SPW_ (SL_ / NW_)        // 4 slices per warp
#define LARGE_ 1.0e6f

__device__ float g_A[NB_ * X_];   // chunk aggregate A
__device__ float g_Bv[NB_ * X_];  // chunk aggregate B
__device__ float g_P[NB_ * X_];   // chunk inclusive prefix value
__device__ int   g_flag[NB_];     // epoch-tagged: 2e+1 aggregate, 2e+2 prefix
__device__ int   g_ticket;        // never reset; epoch = ticket / NB_

__global__ void __launch_bounds__(256, 6) until_scan(const float* __restrict__ phi,
                                                     const float* __restrict__ psi,
                                                     float* __restrict__ out) {
    __shared__ float sA[SL_][X_];     // per-slice aggregate A
    __shared__ float sB[SL_][X_];     // per-slice aggregate B
    __shared__ float sWA[NW_][X_];    // per-warp fold of its 4 slices
    __shared__ float sWB[NW_][X_];
    __shared__ float sGC[NW_][X_];    // carry entering each warp's slice group
    __shared__ int s_tic;

    const int tid = threadIdx.x;
    if (tid == 0) s_tic = atomicAdd(&g_ticket, 1);
    __syncthreads();
    const int traw = s_tic;
    const int e    = traw >> 11;          // epoch (NB_ = 2048)
    const int v    = traw & (NB_ - 1);
    const int b    = v % B_;              // breadth-first over chunks
    const int c    = v / B_;
    const int bc   = b * C_ + c;
    const int FLAG_AGG = 2 * e + 1;
    const int FLAG_PRE = 2 * e + 2;

    const int xg   = tid & 7;             // float4 group along x
    const int xq   = xg * 4;
    const int s    = tid >> 3;            // slice 0..31
    const int w    = tid >> 5;            // warp 0..7 (owns slices 4w..4w+3)
    const int lane = tid & 31;

    const size_t base = (size_t)b * T_ * X_ + (size_t)(c * TC_ + s * PT_) * X_ + xq;
    const float4* pp = (const float4*)(phi + base);
    const float4* qq = (const float4*)(psi + base);

    // ---------- phase 1: streaming slice aggregate (lines land in L2) ----------
    float4 A  = make_float4( CUDART_INF_F,  CUDART_INF_F,  CUDART_INF_F,  CUDART_INF_F);
    float4 Bc = make_float4(-CUDART_INF_F, -CUDART_INF_F, -CUDART_INF_F, -CUDART_INF_F);
#pragma unroll
    for (int i = 0; i < PT_; i++) {
        float4 p = pp[i * (X_ / 4)];
        float4 q = qq[i * (X_ / 4)];
        A.x = fminf(p.x, fmaxf(q.x, A.x));  Bc.x = fmaxf(q.x, Bc.x);
        A.y = fminf(p.y, fmaxf(q.y, A.y));  Bc.y = fmaxf(q.y, Bc.y);
        A.z = fminf(p.z, fmaxf(q.z, A.z));  Bc.z = fmaxf(q.z, Bc.z);
        A.w = fminf(p.w, fmaxf(q.w, A.w));  Bc.w = fmaxf(q.w, Bc.w);
    }
    sA[s][xq + 0] = A.x;  sA[s][xq + 1] = A.y;  sA[s][xq + 2] = A.z;  sA[s][xq + 3] = A.w;
    sB[s][xq + 0] = Bc.x; sB[s][xq + 1] = Bc.y; sB[s][xq + 2] = Bc.z; sB[s][xq + 3] = Bc.w;
    __syncwarp();   // slices 4w..4w+3 are written by warp w's own threads

    // ---------- fold level 1: warp w folds its 4 slices (lane = x) ----------
    {
        float wA =  CUDART_INF_F;
        float wB = -CUDART_INF_F;
#pragma unroll
        for (int j = 0; j < SPW_; j++) {
            const int sl = w * SPW_ + j;
            wA = fminf(sA[sl][lane], fmaxf(sB[sl][lane], wA));
            wB = fmaxf(sB[sl][lane], wB);
        }
        sWA[w][lane] = wA;
        sWB[w][lane] = wB;
    }
    __syncthreads();

    // ---------- warp 0: fold level 2, publish AGG, lookback, carries, PRE ----------
    if (tid < 32) {
        const int x = tid;
        float Ab =  CUDART_INF_F;
        float Bb = -CUDART_INF_F;
#pragma unroll
        for (int j = 0; j < NW_; j++) {
            Ab = fminf(sWA[j][x], fmaxf(sWB[j][x], Ab));
            Bb = fmaxf(sWB[j][x], Bb);
        }

        // Publish aggregate ONLY for c>0: chunk 0 goes straight to prefix,
        // so lookback never crosses a batch boundary.
        if (c > 0) {
            g_A[bc * X_ + x]  = Ab;
            g_Bv[bc * X_ + x] = Bb;
            __threadfence();
            __syncwarp();
            if (x == 0) *(volatile int*)&g_flag[bc] = FLAG_AGG;
        }

        float vin;
        if (c == 0) {
            vin = -LARGE_;
        } else {
            float accA =  CUDART_INF_F;
            float accB = -CUDART_INF_F;
            int j = bc - 1;
            while (true) {
                int f;
                do { f = *(volatile int*)&g_flag[j]; } while (f < FLAG_AGG);
                __threadfence();
                if (f == FLAG_PRE) {
                    vin = fminf(accA, fmaxf(accB, g_P[j * X_ + x]));
                    break;
                }
                float Aj = g_A[j * X_ + x];
                float Bj = g_Bv[j * X_ + x];
                accA = fminf(accA, fmaxf(accB, Aj));
                accB = fmaxf(accB, Bj);
                j--;
            }
        }

        // publish inclusive prefix FIRST (shortest tier-to-tier latency)
        float pre = fminf(Ab, fmaxf(Bb, vin));
        g_P[bc * X_ + x] = pre;
        __threadfence();
        __syncwarp();
        if (x == 0) *(volatile int*)&g_flag[bc] = FLAG_PRE;

        // carries entering each warp's slice group
        float g = vin;
#pragma unroll
        for (int j = 0; j < NW_; j++) {
            sGC[j][x] = g;
            g = fminf(sWA[j][x], fmaxf(sWB[j][x], g));
        }
    }
    __syncthreads();

    // ---------- per-thread slice carry (walk <=3 slices from warp-group carry) ----------
    float v0 = sGC[w][xq + 0];
    float v1 = sGC[w][xq + 1];
    float v2 = sGC[w][xq + 2];
    float v3 = sGC[w][xq + 3];
    for (int j = w * SPW_; j < s; j++) {
        v0 = fminf(sA[j][xq + 0], fmaxf(sB[j][xq + 0], v0));
        v1 = fminf(sA[j][xq + 1], fmaxf(sB[j][xq + 1], v1));
        v2 = fminf(sA[j][xq + 2], fmaxf(sB[j][xq + 2], v2));
        v3 = fminf(sA[j][xq + 3], fmaxf(sB[j][xq + 3], v3));
    }
    float4 vc = make_float4(v0, v1, v2, v3);

    // ---------- phase 2: reload (L2 hits), apply carry, stream out ----------
    float4* oo = (float4*)(out + base);
#pragma unroll
    for (int i = 0; i < PT_; i++) {
        float4 p = __ldcs(&pp[i * (X_ / 4)]);
        float4 q = __ldcs(&qq[i * (X_ / 4)]);
        vc.x = fminf(p.x, fmaxf(q.x, vc.x));
        vc.y = fminf(p.y, fmaxf(q.y, vc.y));
        vc.z = fminf(p.z, fmaxf(q.z, vc.z));
        vc.w = fminf(p.w, fmaxf(q.w, vc.w));
        __stcs(&oo[i * (X_ / 4)], vc);
    }
}

extern "C" void kernel_launch(void* const* d_in, const int* in_sizes, int n_in,
                              void* d_out, int out_size) {
    const float* phi = (const float*)d_in[0];
    const float* psi = (const float*)d_in[1];
    float* out = (float*)d_out;

    until_scan<<<NB_, 256>>>(phi, psi, out);
}